// round 8
// baseline (speedup 1.0000x reference)
#include <cuda_runtime.h>
#include <cuda_bf16.h>
#include <cstdint>

// Problem constants
constexpr int Bn = 8, Sn = 2048, Dn = 2048, Rn = 512, En = 8;
constexpr int Mn = Bn * Sn;  // 16384 tokens

// Scratch (device globals: allocation-free rule)
__device__ __align__(1024) int8_t g_xq[(size_t)Mn * Dn];   // 32 MB LN'd acts, int8
__device__ __align__(1024) int8_t g_w1q[(size_t)Rn * Dn];  // 1 MB w1^T int8 [R,D]
__device__ float g_sA[Mn];            // per-token act scale
__device__ float g_sB[Rn];            // per-column w1 scale
__device__ unsigned g_sBmax[Rn];      // column max |w1| as uint bits
__device__ float g_H[Bn * Rn];        // per-batch sum of GELU outputs
__device__ float g_T[Bn * Rn];        // per-batch T = H@w2 + S*b2 (seeded)

// ---------------------------------------------------------------------------
__device__ __forceinline__ void cp_async16(uint32_t smem_dst, const void* gmem_src) {
    asm volatile("cp.async.cg.shared.global [%0], [%1], 16;\n" :: "r"(smem_dst), "l"(gmem_src));
}
#define CP_COMMIT() asm volatile("cp.async.commit_group;\n" ::)

__device__ __forceinline__ float gelu_exact(float x) {
    return 0.5f * x * (1.f + erff(x * 0.7071067811865475f));
}

__device__ __forceinline__ void imma16832(int* c, const uint32_t* a, uint32_t b0, uint32_t b1) {
    asm volatile(
        "mma.sync.aligned.m16n8k32.row.col.s32.s8.s8.s32 "
        "{%0,%1,%2,%3}, {%4,%5,%6,%7}, {%8,%9}, {%0,%1,%2,%3};"
        : "+r"(c[0]), "+r"(c[1]), "+r"(c[2]), "+r"(c[3])
        : "r"(a[0]), "r"(a[1]), "r"(a[2]), "r"(a[3]), "r"(b0), "r"(b1));
}

__device__ __forceinline__ int8_t quant_clamp(float v) {
    int q = __float2int_rn(v);
    q = max(-127, min(127, q));
    return (int8_t)q;
}

// ---------------------------------------------------------------------------
// Kernel 0: zero sBmax/H, seed T with S*b2
// ---------------------------------------------------------------------------
__global__ void prep_kernel(const float* __restrict__ b2) {
    int idx = blockIdx.x * blockDim.x + threadIdx.x;
    if (idx < Rn) g_sBmax[idx] = 0u;
    if (idx < Bn * Rn) {
        g_H[idx] = 0.f;
        g_T[idx] = (float)Sn * b2[idx & (Rn - 1)];
    }
}

// ---------------------------------------------------------------------------
// Kernel 1: column max |w1| (w1 is [D,R] fp32) -> g_sBmax (uint bits)
// ---------------------------------------------------------------------------
__global__ void colmax_kernel(const float* __restrict__ w1) {
    const int r = threadIdx.x;               // 512 threads
    const int d0 = blockIdx.x * 256;         // 8 blocks
    float m = 0.f;
    #pragma unroll 4
    for (int i = 0; i < 256; ++i)
        m = fmaxf(m, fabsf(w1[(size_t)(d0 + i) * Rn + r]));
    atomicMax(&g_sBmax[r], __float_as_uint(m));
}

// ---------------------------------------------------------------------------
// Kernel 2: transpose + quantize w1 [D,R] fp32 -> g_w1q [R,D] int8; write g_sB
// ---------------------------------------------------------------------------
__global__ void transq_kernel(const float* __restrict__ w1) {
    __shared__ float tile[32][33];
    const int r0 = blockIdx.x * 32;  // 16
    const int d0 = blockIdx.y * 32;  // 64
    const int tx = threadIdx.x, ty = threadIdx.y;  // (32, 8)
    #pragma unroll
    for (int j = 0; j < 32; j += 8)
        tile[ty + j][tx] = w1[(size_t)(d0 + ty + j) * Rn + r0 + tx];
    __syncthreads();
    #pragma unroll
    for (int j = 0; j < 32; j += 8) {
        const int r = r0 + ty + j;
        const float mx = __uint_as_float(g_sBmax[r]);
        const float inv = (mx > 0.f) ? 127.f / mx : 0.f;
        g_w1q[(size_t)r * Dn + d0 + tx] = quant_clamp(tile[tx][ty + j] * inv);
        if (blockIdx.y == 0 && tx == 0) g_sB[r] = mx * (1.f / 127.f);
    }
}

// ---------------------------------------------------------------------------
// Kernel 3: LayerNorm per token + per-row symmetric int8 quantization
// ---------------------------------------------------------------------------
__global__ void ln_kernel(const float* __restrict__ hs,
                          const float* __restrict__ gamma,
                          const float* __restrict__ beta) {
    const int token = blockIdx.x;
    const int t = threadIdx.x;  // 256
    const float4* row = reinterpret_cast<const float4*>(hs + (size_t)token * Dn);
    float4 v0 = row[t];
    float4 v1 = row[t + 256];
    float s  = v0.x + v0.y + v0.z + v0.w + v1.x + v1.y + v1.z + v1.w;
    float ss = v0.x*v0.x + v0.y*v0.y + v0.z*v0.z + v0.w*v0.w
             + v1.x*v1.x + v1.y*v1.y + v1.z*v1.z + v1.w*v1.w;
    #pragma unroll
    for (int o = 16; o; o >>= 1) {
        s  += __shfl_xor_sync(0xFFFFFFFFu, s,  o);
        ss += __shfl_xor_sync(0xFFFFFFFFu, ss, o);
    }
    __shared__ float rs[8], rss[8];
    const int w = t >> 5, l = t & 31;
    if (l == 0) { rs[w] = s; rss[w] = ss; }
    __syncthreads();
    if (t < 32) {
        float a = (t < 8) ? rs[t] : 0.f;
        float c = (t < 8) ? rss[t] : 0.f;
        #pragma unroll
        for (int o = 4; o; o >>= 1) {
            a += __shfl_xor_sync(0xFFFFFFFFu, a, o);
            c += __shfl_xor_sync(0xFFFFFFFFu, c, o);
        }
        if (t == 0) { rs[0] = a; rss[0] = c; }
    }
    __syncthreads();
    const float mu   = rs[0] * (1.f / Dn);
    const float var  = rss[0] * (1.f / Dn) - mu * mu;
    const float rstd = rsqrtf(var + 1e-5f);

    const float4* g4 = reinterpret_cast<const float4*>(gamma);
    const float4* b4 = reinterpret_cast<const float4*>(beta);
    float y[8];
    {
        float4 g = g4[t], bb = b4[t];
        y[0] = (v0.x-mu)*rstd*g.x+bb.x;  y[1] = (v0.y-mu)*rstd*g.y+bb.y;
        y[2] = (v0.z-mu)*rstd*g.z+bb.z;  y[3] = (v0.w-mu)*rstd*g.w+bb.w;
    }
    {
        float4 g = g4[t+256], bb = b4[t+256];
        y[4] = (v1.x-mu)*rstd*g.x+bb.x;  y[5] = (v1.y-mu)*rstd*g.y+bb.y;
        y[6] = (v1.z-mu)*rstd*g.z+bb.z;  y[7] = (v1.w-mu)*rstd*g.w+bb.w;
    }
    // row max |y|
    float m = 0.f;
    #pragma unroll
    for (int i = 0; i < 8; ++i) m = fmaxf(m, fabsf(y[i]));
    #pragma unroll
    for (int o = 16; o; o >>= 1) m = fmaxf(m, __shfl_xor_sync(0xFFFFFFFFu, m, o));
    __syncthreads();  // rs[0] consumed by all; safe to reuse
    if (l == 0) rs[w] = m;
    __syncthreads();
    if (t < 32) {
        float a = (t < 8) ? rs[t] : 0.f;
        #pragma unroll
        for (int o = 4; o; o >>= 1) a = fmaxf(a, __shfl_xor_sync(0xFFFFFFFFu, a, o));
        if (t == 0) rs[0] = a;
    }
    __syncthreads();
    const float mx = rs[0];
    const float inv_s = (mx > 0.f) ? 127.f / mx : 0.f;

    char4* out = reinterpret_cast<char4*>(g_xq + (size_t)token * Dn);
    out[t]       = make_char4((char)quant_clamp(y[0]*inv_s), (char)quant_clamp(y[1]*inv_s),
                              (char)quant_clamp(y[2]*inv_s), (char)quant_clamp(y[3]*inv_s));
    out[t + 256] = make_char4((char)quant_clamp(y[4]*inv_s), (char)quant_clamp(y[5]*inv_s),
                              (char)quant_clamp(y[6]*inv_s), (char)quant_clamp(y[7]*inv_s));
    if (t == 0) g_sA[token] = mx * (1.f / 127.f);
}

// ---------------------------------------------------------------------------
// Kernel 4: INT8 GEMM (xq @ w1q^T) + de-scale + bias + GELU + column reduce
//   BM=128 BN=128 BK=64(bytes), 256 threads (8 warps, warp tile 32x64),
//   4-stage cp.async pipe, one sync/iter, fragment prefetch.
// ---------------------------------------------------------------------------
constexpr int BM = 128, BN = 128, BK = 64;
constexpr int STAGES = 4;
constexpr int ROWB = 80;                     // 64B data + 16B pad per row
constexpr int A_BUF = BM * ROWB;             // 10240 B
constexpr int B_BUF = BN * ROWB;             // 10240 B
constexpr int SMEM_BYTES = STAGES * (A_BUF + B_BUF);  // 81920

__global__ __launch_bounds__(256) void gemm_kernel(const float* __restrict__ b1) {
    extern __shared__ __align__(1024) unsigned char smem[];
    unsigned char* sA = smem;
    unsigned char* sB = smem + STAGES * A_BUF;
    __shared__ float sAs[BM], sBs[BN], b1s[BN];
    __shared__ float part[4][BN];

    const int tid = threadIdx.x;
    const int bn = blockIdx.x;   // 0..3
    const int bm = blockIdx.y;   // 0..127
    const int warp = tid >> 5, lane = tid & 31;
    const int wm = warp >> 1, wn = warp & 1;

    const uint32_t asBase = (uint32_t)__cvta_generic_to_shared(sA);
    const uint32_t bsBase = (uint32_t)__cvta_generic_to_shared(sB);

    // scales + bias into smem (consumed after the k-loop; syncs inside loop cover it)
    if (tid < 128) {
        sAs[tid] = g_sA[bm * BM + tid];
        sBs[tid] = g_sB[bn * BN + tid];
        b1s[tid] = __ldg(b1 + bn * BN + tid);
    }

    int acc[2][8][4];
    #pragma unroll
    for (int i = 0; i < 2; ++i)
        #pragma unroll
        for (int j = 0; j < 8; ++j)
            #pragma unroll
            for (int k = 0; k < 4; ++k) acc[i][j][k] = 0;

    // gmem loads: 512 16B chunks per stage per matrix; 2 per thread each
    const int c_row = tid >> 2;            // 0..63
    const int c_off = (tid & 3) * 16;      // 0/16/32/48
    const int8_t* gA0 = g_xq + (size_t)(bm * BM + c_row) * Dn + c_off;
    const int8_t* gA1 = gA0 + (size_t)64 * Dn;
    const int8_t* gB0 = g_w1q + (size_t)(bn * BN + c_row) * Dn + c_off;
    const int8_t* gB1 = gB0 + (size_t)64 * Dn;

    const uint32_t adst0 = asBase + (uint32_t)(c_row * ROWB + c_off);
    const uint32_t adst1 = adst0 + 64u * ROWB;
    const uint32_t bdst0 = bsBase + (uint32_t)(c_row * ROWB + c_off);
    const uint32_t bdst1 = bdst0 + 64u * ROWB;

    // ldmatrix bases (stage 0, ksi 0), byte addressed
    // A x4 tiles: (r0-7,k0-15)(r8-15,k0-15)(r0-7,k16-31)(r8-15,k16-31)
    uint32_t abase[2];
    #pragma unroll
    for (int im = 0; im < 2; ++im)
        abase[im] = asBase + (uint32_t)((wm * 32 + im * 16 + (((lane >> 3) & 1) << 3)
                                         + (lane & 7)) * ROWB + ((lane >> 4) << 4));
    // B x4 tiles: (n g,k0-15)(n g,k16-31)(n g+8,k0-15)(n g+8,k16-31)
    uint32_t bbase[4];
    #pragma unroll
    for (int jq = 0; jq < 4; ++jq)
        bbase[jq] = bsBase + (uint32_t)((wn * 64 + jq * 16 + ((lane >> 4) << 3)
                                         + (lane & 7)) * ROWB + (((lane >> 3) & 1) << 4));

    constexpr int KT = Dn / BK;  // 32

    auto load_stage = [&](int kt, int stg) {
        const int k0 = kt * BK;
        const uint32_t ao = (uint32_t)(stg * A_BUF);
        const uint32_t bo = (uint32_t)(stg * B_BUF);
        cp_async16(adst0 + ao, gA0 + k0);
        cp_async16(adst1 + ao, gA1 + k0);
        cp_async16(bdst0 + bo, gB0 + k0);
        cp_async16(bdst1 + bo, gB1 + k0);
    };

    load_stage(0, 0); CP_COMMIT();
    load_stage(1, 1); CP_COMMIT();
    load_stage(2, 2); CP_COMMIT();

    for (int kt0 = 0; kt0 < KT; kt0 += STAGES) {
        #pragma unroll
        for (int s = 0; s < STAGES; ++s) {
            const int kt = kt0 + s;
            asm volatile("cp.async.wait_group 2;\n" ::);
            __syncthreads();
            if (kt + 3 < KT) load_stage(kt + 3, (s + 3) & 3);
            CP_COMMIT();

            const uint32_t ao = (uint32_t)(s * A_BUF);
            const uint32_t bo = (uint32_t)(s * B_BUF);

            uint32_t ra[2][2][4];  // [ksi][im]
            #pragma unroll
            for (int ksi = 0; ksi < 2; ++ksi)
                #pragma unroll
                for (int im = 0; im < 2; ++im)
                    asm volatile("ldmatrix.sync.aligned.m8n8.x4.shared.b16 {%0,%1,%2,%3}, [%4];"
                        : "=r"(ra[ksi][im][0]), "=r"(ra[ksi][im][1]),
                          "=r"(ra[ksi][im][2]), "=r"(ra[ksi][im][3])
                        : "r"(abase[im] + ao + ksi * 32));

            uint32_t rb[4][4];
            #pragma unroll
            for (int jq = 0; jq < 4; ++jq)
                asm volatile("ldmatrix.sync.aligned.m8n8.x4.shared.b16 {%0,%1,%2,%3}, [%4];"
                    : "=r"(rb[jq][0]), "=r"(rb[jq][1]), "=r"(rb[jq][2]), "=r"(rb[jq][3])
                    : "r"(bbase[jq] + bo));
            #pragma unroll
            for (int im = 0; im < 2; ++im)
                #pragma unroll
                for (int j = 0; j < 8; ++j)
                    imma16832(acc[im][j], ra[0][im],
                              rb[j >> 1][(j & 1) * 2], rb[j >> 1][(j & 1) * 2 + 1]);

            #pragma unroll
            for (int jq = 0; jq < 4; ++jq)
                asm volatile("ldmatrix.sync.aligned.m8n8.x4.shared.b16 {%0,%1,%2,%3}, [%4];"
                    : "=r"(rb[jq][0]), "=r"(rb[jq][1]), "=r"(rb[jq][2]), "=r"(rb[jq][3])
                    : "r"(bbase[jq] + bo + 32));
            #pragma unroll
            for (int im = 0; im < 2; ++im)
                #pragma unroll
                for (int j = 0; j < 8; ++j)
                    imma16832(acc[im][j], ra[1][im],
                              rb[j >> 1][(j & 1) * 2], rb[j >> 1][(j & 1) * 2 + 1]);
        }
    }
    __syncthreads();

    // Epilogue: de-scale + bias + GELU + column sums
    const int g = lane >> 2, tq = lane & 3;
    const int batch = bm >> 4;
    float sa[2][2];
    #pragma unroll
    for (int im = 0; im < 2; ++im) {
        sa[im][0] = sAs[wm * 32 + im * 16 + g];
        sa[im][1] = sAs[wm * 32 + im * 16 + g + 8];
    }
    #pragma unroll
    for (int j = 0; j < 8; ++j) {
        const int cb = wn * 64 + j * 8 + tq * 2;
        const float sb0 = sBs[cb], sb1 = sBs[cb + 1];
        const float q0 = b1s[cb], q1 = b1s[cb + 1];
        float s0 = 0.f, s1 = 0.f;
        #pragma unroll
        for (int im = 0; im < 2; ++im) {
            s0 += gelu_exact((float)acc[im][j][0] * sa[im][0] * sb0 + q0)
                + gelu_exact((float)acc[im][j][2] * sa[im][1] * sb0 + q0);
            s1 += gelu_exact((float)acc[im][j][1] * sa[im][0] * sb1 + q1)
                + gelu_exact((float)acc[im][j][3] * sa[im][1] * sb1 + q1);
        }
        #pragma unroll
        for (int o = 4; o <= 16; o <<= 1) {
            s0 += __shfl_xor_sync(0xFFFFFFFFu, s0, o);
            s1 += __shfl_xor_sync(0xFFFFFFFFu, s1, o);
        }
        if (lane < 4) {
            part[wm][wn * 64 + j * 8 + lane * 2]     = s0;
            part[wm][wn * 64 + j * 8 + lane * 2 + 1] = s1;
        }
    }
    __syncthreads();
    if (tid < BN) {
        float v = part[0][tid] + part[1][tid] + part[2][tid] + part[3][tid];
        atomicAdd(&g_H[batch * Rn + bn * BN + tid], v);
    }
}

// ---------------------------------------------------------------------------
// Kernel 5: T += H @ w2  (K-split)  grid (col8, batch8, kseg4) x 256 threads
// ---------------------------------------------------------------------------
__global__ void tail_kernel(const float* __restrict__ w2) {
    __shared__ float sH[128];
    __shared__ float part[4][64];
    const int b  = blockIdx.y;
    const int c0 = blockIdx.x * 64;
    const int k0 = blockIdx.z * 128;
    const int tid = threadIdx.x;
    if (tid < 128) sH[tid] = g_H[b * Rn + k0 + tid];
    __syncthreads();
    const int col = tid & 63, ks = tid >> 6;
    float a = 0.f;
    const float* w2p = w2 + (size_t)(k0 + ks * 32) * Rn + c0 + col;
    #pragma unroll 8
    for (int r = 0; r < 32; ++r)
        a = fmaf(sH[ks * 32 + r], w2p[(size_t)r * Rn], a);
    part[ks][col] = a;
    __syncthreads();
    if (tid < 64) {
        float t = part[0][tid] + part[1][tid] + part[2][tid] + part[3][tid];
        atomicAdd(&g_T[b * Rn + c0 + tid], t);
    }
}

// ---------------------------------------------------------------------------
// Kernel 6: logits = T @ wr + br ; aux loss + mode
// ---------------------------------------------------------------------------
__global__ void final_kernel(const float* __restrict__ wr, const float* __restrict__ br,
                             float* out, int out_size) {
    __shared__ float sl[64];
    const int t = threadIdx.x;
    if (t < 64) {
        const int b = t >> 3, e = t & 7;
        float lg = br[e];
        #pragma unroll 8
        for (int q = 0; q < Rn; ++q) lg = fmaf(g_T[b * Rn + q], wr[q * En + e], lg);
        sl[t] = lg;
    }
    __syncthreads();
    if (t == 0) {
        float aux = 0.f;
        int counts[En] = {};
        for (int b = 0; b < Bn; ++b) {
            const float* l = &sl[b * En];
            int best = 0;
            for (int e = 1; e < En; ++e)
                if (l[e] > l[best]) best = e;
            counts[best]++;
            for (int e = 0; e < En; ++e) {
                float x = l[e];
                float sp = fmaxf(x, 0.f) + log1pf(expf(-fabsf(x)));
                aux += sp - (e == best ? x : 0.f);
            }
        }
        aux *= (1.f / (Bn * En));
        int nxt = 0;
        for (int e = 1; e < En; ++e)
            if (counts[e] > counts[nxt]) nxt = e;
        out[0] = aux;
        if (out_size > 1) out[1] = (float)nxt;
    }
}

// ---------------------------------------------------------------------------
extern "C" void kernel_launch(void* const* d_in, const int* in_sizes, int n_in,
                              void* d_out, int out_size) {
    const float* hs    = (const float*)d_in[0];
    const float* gamma = (const float*)d_in[1];
    const float* beta  = (const float*)d_in[2];
    const float* w1    = (const float*)d_in[3];
    const float* b1    = (const float*)d_in[4];
    const float* w2    = (const float*)d_in[5];
    const float* b2    = (const float*)d_in[6];
    const float* wr    = (const float*)d_in[7];
    const float* br    = (const float*)d_in[8];

    cudaFuncSetAttribute(gemm_kernel, cudaFuncAttributeMaxDynamicSharedMemorySize, SMEM_BYTES);

    prep_kernel<<<(Bn * Rn + 255) / 256, 256>>>(b2);         // idx 0
    colmax_kernel<<<8, 512>>>(w1);                            // idx 1
    transq_kernel<<<dim3(Rn / 32, Dn / 32), dim3(32, 8)>>>(w1); // idx 2
    ln_kernel<<<Mn, 256>>>(hs, gamma, beta);                  // idx 3 (profiled)
    gemm_kernel<<<dim3(Rn / BN, Mn / BM), 256, SMEM_BYTES>>>(b1);
    tail_kernel<<<dim3(8, Bn, 4), 256>>>(w2);
    final_kernel<<<1, 64>>>(wr, br, (float*)d_out, out_size);
}

// round 9
// speedup vs baseline: 2.0646x; 2.0646x over previous
#include <cuda_runtime.h>
#include <cuda_fp16.h>
#include <cstdint>

// Problem constants
constexpr int Bn = 8, Sn = 2048, Dn = 2048, Rn = 512, En = 8;
constexpr int Mn = Bn * Sn;  // 16384 tokens

// Scratch (device globals: allocation-free rule)
__device__ __align__(1024) __half g_xh[(size_t)Mn * Dn];   // 64 MB LN'd acts, fp16
__device__ __align__(1024) __half g_w1h[(size_t)Dn * Rn];  // 2 MB w1 fp16 [D,R]
__device__ float g_H[Bn * Rn];   // per-batch sum of GELU outputs
__device__ float g_T[Bn * Rn];   // per-batch T = H@w2 + S*b2 (seeded)

// ---------------------------------------------------------------------------
__device__ __forceinline__ void cp_async16(uint32_t smem_dst, const void* gmem_src) {
    asm volatile("cp.async.cg.shared.global [%0], [%1], 16;\n" :: "r"(smem_dst), "l"(gmem_src));
}
#define CP_COMMIT() asm volatile("cp.async.commit_group;\n" ::)

__device__ __forceinline__ float gelu_exact(float x) {
    return 0.5f * x * (1.f + erff(x * 0.7071067811865475f));
}

// fp16-accumulate HMMA: D(f16x2 pair) = A*B + C
__device__ __forceinline__ void mma16816_f16(uint32_t* c, const uint32_t* a,
                                             uint32_t b0, uint32_t b1) {
    asm volatile(
        "mma.sync.aligned.m16n8k16.row.col.f16.f16.f16.f16 "
        "{%0,%1}, {%2,%3,%4,%5}, {%6,%7}, {%0,%1};"
        : "+r"(c[0]), "+r"(c[1])
        : "r"(a[0]), "r"(a[1]), "r"(a[2]), "r"(a[3]), "r"(b0), "r"(b1));
}

// ---------------------------------------------------------------------------
// Kernel 1: cast w1 -> fp16 ([D,R] layout), zero H, seed T with S*b2
// ---------------------------------------------------------------------------
__global__ void prep_kernel(const float* __restrict__ w1, const float* __restrict__ b2) {
    int idx = blockIdx.x * blockDim.x + threadIdx.x;
    if (idx < Dn * Rn) g_w1h[idx] = __float2half(w1[idx]);
    if (idx < Bn * Rn) {
        g_H[idx] = 0.f;
        g_T[idx] = (float)Sn * b2[idx & (Rn - 1)];
    }
}

// ---------------------------------------------------------------------------
// Kernel 2: LayerNorm per token, write fp16
// ---------------------------------------------------------------------------
__global__ void ln_kernel(const float* __restrict__ hs,
                          const float* __restrict__ gamma,
                          const float* __restrict__ beta) {
    const int token = blockIdx.x;
    const int t = threadIdx.x;
    const float4* row = reinterpret_cast<const float4*>(hs + (size_t)token * Dn);
    float4 v0 = row[t];
    float4 v1 = row[t + 256];
    float s  = v0.x + v0.y + v0.z + v0.w + v1.x + v1.y + v1.z + v1.w;
    float ss = v0.x*v0.x + v0.y*v0.y + v0.z*v0.z + v0.w*v0.w
             + v1.x*v1.x + v1.y*v1.y + v1.z*v1.z + v1.w*v1.w;
    #pragma unroll
    for (int o = 16; o; o >>= 1) {
        s  += __shfl_xor_sync(0xFFFFFFFFu, s,  o);
        ss += __shfl_xor_sync(0xFFFFFFFFu, ss, o);
    }
    __shared__ float rs[8], rss[8];
    const int w = t >> 5, l = t & 31;
    if (l == 0) { rs[w] = s; rss[w] = ss; }
    __syncthreads();
    if (t < 32) {
        float a = (t < 8) ? rs[t] : 0.f;
        float c = (t < 8) ? rss[t] : 0.f;
        #pragma unroll
        for (int o = 4; o; o >>= 1) {
            a += __shfl_xor_sync(0xFFFFFFFFu, a, o);
            c += __shfl_xor_sync(0xFFFFFFFFu, c, o);
        }
        if (t == 0) { rs[0] = a; rss[0] = c; }
    }
    __syncthreads();
    const float mu   = rs[0] * (1.f / Dn);
    const float var  = rss[0] * (1.f / Dn) - mu * mu;
    const float rstd = rsqrtf(var + 1e-5f);

    const float4* g4 = reinterpret_cast<const float4*>(gamma);
    const float4* b4 = reinterpret_cast<const float4*>(beta);
    __half2* out2 = reinterpret_cast<__half2*>(g_xh + (size_t)token * Dn);
    {
        float4 g = g4[t], bb = b4[t];
        out2[2*t]   = __floats2half2_rn((v0.x-mu)*rstd*g.x+bb.x, (v0.y-mu)*rstd*g.y+bb.y);
        out2[2*t+1] = __floats2half2_rn((v0.z-mu)*rstd*g.z+bb.z, (v0.w-mu)*rstd*g.w+bb.w);
    }
    {
        int t2 = t + 256;
        float4 g = g4[t2], bb = b4[t2];
        out2[2*t2]   = __floats2half2_rn((v1.x-mu)*rstd*g.x+bb.x, (v1.y-mu)*rstd*g.y+bb.y);
        out2[2*t2+1] = __floats2half2_rn((v1.z-mu)*rstd*g.z+bb.z, (v1.w-mu)*rstd*g.w+bb.w);
    }
}

// ---------------------------------------------------------------------------
// nop: shifts the ncu capture slot onto the GEMM
// ---------------------------------------------------------------------------
__global__ void nop_kernel() {}

// ---------------------------------------------------------------------------
// Kernel 3: GEMM (xh @ w1h) fp16-acc + f32 promotion every 8 k-iters
//   BM=128 BN=64 BK=32, 256 threads (8 warps, warp tile 32x32), 4-stage pipe,
//   one sync per iter, fragment prefetch. Epilogue: +b1, GELU, column reduce.
// ---------------------------------------------------------------------------
constexpr int BM = 128, BN = 64, BK = 32;
constexpr int STAGES = 4;
constexpr int ASTR = 40;   // fp16 elems per A row (pad 32->40)
constexpr int BSTR = 72;   // fp16 elems per B row (pad 64->72)
constexpr int A_BUF = BM * ASTR;   // 5120
constexpr int B_BUF = BK * BSTR;   // 2304
constexpr int SMEM_BYTES = STAGES * (A_BUF + B_BUF) * 2;  // 59392

__global__ __launch_bounds__(256) void gemm_kernel(const float* __restrict__ b1) {
    extern __shared__ __align__(1024) unsigned char smem[];
    __half* sA = reinterpret_cast<__half*>(smem);
    __half* sB = sA + STAGES * A_BUF;
    __shared__ float part[4][BN];

    const int tid = threadIdx.x;
    const int bn = blockIdx.x;   // 0..7
    const int bm = blockIdx.y;   // 0..127
    const int warp = tid >> 5, lane = tid & 31;
    const int wm = warp >> 1, wn = warp & 1;

    const uint32_t asBase = (uint32_t)__cvta_generic_to_shared(sA);
    const uint32_t bsBase = (uint32_t)__cvta_generic_to_shared(sB);

    float facc[2][4][4];   // fp32 shadow accumulators
    uint32_t hacc[2][4][2];  // fp16 running accumulators (f16x2 pairs)
    #pragma unroll
    for (int i = 0; i < 2; ++i)
        #pragma unroll
        for (int j = 0; j < 4; ++j) {
            #pragma unroll
            for (int k = 0; k < 4; ++k) facc[i][j][k] = 0.f;
            hacc[i][j][0] = 0u; hacc[i][j][1] = 0u;
        }

    const int a_r = tid >> 2, a_c = (tid & 3) * 8;
    const int b_r = tid >> 3, b_c = (tid & 7) * 8;
    const __half* gA0 = g_xh + (size_t)(bm * BM + a_r) * Dn + a_c;
    const __half* gA1 = gA0 + (size_t)64 * Dn;
    const __half* gB0 = g_w1h + (size_t)b_r * Rn + bn * BN + b_c;

    const uint32_t adst0 = asBase + 2u * (uint32_t)(a_r * ASTR + a_c);
    const uint32_t adst1 = asBase + 2u * (uint32_t)((a_r + 64) * ASTR + a_c);
    const uint32_t bdst0 = bsBase + 2u * (uint32_t)(b_r * BSTR + b_c);

    uint32_t abase[2], bbase[2];
    #pragma unroll
    for (int im = 0; im < 2; ++im)
        abase[im] = asBase + 2u * (uint32_t)((wm * 32 + im * 16 + (lane & 15)) * ASTR
                                             + ((lane >> 4) << 3));
    #pragma unroll
    for (int jn = 0; jn < 2; ++jn)
        bbase[jn] = bsBase + 2u * (uint32_t)((lane & 15) * BSTR
                                             + wn * 32 + jn * 16 + ((lane >> 4) << 3));

    constexpr int KT = Dn / BK;  // 64

    auto load_stage = [&](int kt, int stg) {
        const int k0 = kt * BK;
        const uint32_t ao = 2u * (uint32_t)(stg * A_BUF);
        const uint32_t bo = 2u * (uint32_t)(stg * B_BUF);
        cp_async16(adst0 + ao, gA0 + k0);
        cp_async16(adst1 + ao, gA1 + k0);
        cp_async16(bdst0 + bo, gB0 + (size_t)k0 * Rn);
    };

    load_stage(0, 0); CP_COMMIT();
    load_stage(1, 1); CP_COMMIT();
    load_stage(2, 2); CP_COMMIT();

    for (int kt0 = 0; kt0 < KT; kt0 += 8) {
        #pragma unroll
        for (int si = 0; si < 8; ++si) {
            const int kt = kt0 + si;
            const int s = kt & 3;
            asm volatile("cp.async.wait_group 2;\n" ::);
            __syncthreads();
            if (kt + 3 < KT) load_stage(kt + 3, (kt + 3) & 3);
            CP_COMMIT();

            const uint32_t aoff0 = 2u * (uint32_t)(s * A_BUF);
            const uint32_t aoff1 = 2u * (uint32_t)(s * A_BUF + 16);
            const uint32_t boff0 = 2u * (uint32_t)(s * B_BUF);
            const uint32_t boff1 = 2u * (uint32_t)(s * B_BUF + 16 * BSTR);

            uint32_t ra[2][2][4];  // [ks][im]
            #pragma unroll
            for (int im = 0; im < 2; ++im)
                asm volatile("ldmatrix.sync.aligned.m8n8.x4.shared.b16 {%0,%1,%2,%3}, [%4];"
                    : "=r"(ra[0][im][0]), "=r"(ra[0][im][1]), "=r"(ra[0][im][2]), "=r"(ra[0][im][3])
                    : "r"(abase[im] + aoff0));
            #pragma unroll
            for (int im = 0; im < 2; ++im)
                asm volatile("ldmatrix.sync.aligned.m8n8.x4.shared.b16 {%0,%1,%2,%3}, [%4];"
                    : "=r"(ra[1][im][0]), "=r"(ra[1][im][1]), "=r"(ra[1][im][2]), "=r"(ra[1][im][3])
                    : "r"(abase[im] + aoff1));

            uint32_t rb[2][4];
            #pragma unroll
            for (int jn = 0; jn < 2; ++jn)
                asm volatile("ldmatrix.sync.aligned.m8n8.x4.trans.shared.b16 {%0,%1,%2,%3}, [%4];"
                    : "=r"(rb[jn][0]), "=r"(rb[jn][1]), "=r"(rb[jn][2]), "=r"(rb[jn][3])
                    : "r"(bbase[jn] + boff0));
            #pragma unroll
            for (int im = 0; im < 2; ++im)
                #pragma unroll
                for (int jn = 0; jn < 2; ++jn) {
                    mma16816_f16(hacc[im][jn * 2 + 0], ra[0][im], rb[jn][0], rb[jn][1]);
                    mma16816_f16(hacc[im][jn * 2 + 1], ra[0][im], rb[jn][2], rb[jn][3]);
                }

            #pragma unroll
            for (int jn = 0; jn < 2; ++jn)
                asm volatile("ldmatrix.sync.aligned.m8n8.x4.trans.shared.b16 {%0,%1,%2,%3}, [%4];"
                    : "=r"(rb[jn][0]), "=r"(rb[jn][1]), "=r"(rb[jn][2]), "=r"(rb[jn][3])
                    : "r"(bbase[jn] + boff1));
            #pragma unroll
            for (int im = 0; im < 2; ++im)
                #pragma unroll
                for (int jn = 0; jn < 2; ++jn) {
                    mma16816_f16(hacc[im][jn * 2 + 0], ra[1][im], rb[jn][0], rb[jn][1]);
                    mma16816_f16(hacc[im][jn * 2 + 1], ra[1][im], rb[jn][2], rb[jn][3]);
                }
        }
        // promote fp16 partials into fp32 shadow, reset fp16 accumulators
        #pragma unroll
        for (int im = 0; im < 2; ++im)
            #pragma unroll
            for (int j = 0; j < 4; ++j) {
                float2 lo = __half22float2(*reinterpret_cast<__half2*>(&hacc[im][j][0]));
                float2 hi = __half22float2(*reinterpret_cast<__half2*>(&hacc[im][j][1]));
                facc[im][j][0] += lo.x; facc[im][j][1] += lo.y;
                facc[im][j][2] += hi.x; facc[im][j][3] += hi.y;
                hacc[im][j][0] = 0u; hacc[im][j][1] = 0u;
            }
    }
    __syncthreads();

    // Epilogue: bias + GELU + warp-level column sums
    const int tq = lane & 3;
    const int batch = bm >> 4;
    #pragma unroll
    for (int j = 0; j < 4; ++j) {
        const int gc = bn * BN + wn * 32 + j * 8 + tq * 2;
        const float bi0 = __ldg(b1 + gc), bi1 = __ldg(b1 + gc + 1);
        float s0 = 0.f, s1 = 0.f;
        #pragma unroll
        for (int im = 0; im < 2; ++im) {
            s0 += gelu_exact(facc[im][j][0] + bi0) + gelu_exact(facc[im][j][2] + bi0);
            s1 += gelu_exact(facc[im][j][1] + bi1) + gelu_exact(facc[im][j][3] + bi1);
        }
        #pragma unroll
        for (int o = 4; o <= 16; o <<= 1) {
            s0 += __shfl_xor_sync(0xFFFFFFFFu, s0, o);
            s1 += __shfl_xor_sync(0xFFFFFFFFu, s1, o);
        }
        if (lane < 4) {
            part[wm][wn * 32 + j * 8 + lane * 2]     = s0;
            part[wm][wn * 32 + j * 8 + lane * 2 + 1] = s1;
        }
    }
    __syncthreads();
    if (tid < BN) {
        float s = part[0][tid] + part[1][tid] + part[2][tid] + part[3][tid];
        atomicAdd(&g_H[batch * Rn + bn * BN + tid], s);
    }
}

// ---------------------------------------------------------------------------
// Kernel 4: T += H @ w2  (K-split)  grid (col8, batch8, kseg4) x 256 threads
// ---------------------------------------------------------------------------
__global__ void tail_kernel(const float* __restrict__ w2) {
    __shared__ float sH[128];
    __shared__ float part[4][64];
    const int b  = blockIdx.y;
    const int c0 = blockIdx.x * 64;
    const int k0 = blockIdx.z * 128;
    const int tid = threadIdx.x;
    if (tid < 128) sH[tid] = g_H[b * Rn + k0 + tid];
    __syncthreads();
    const int col = tid & 63, ks = tid >> 6;
    float a = 0.f;
    const float* w2p = w2 + (size_t)(k0 + ks * 32) * Rn + c0 + col;
    #pragma unroll 8
    for (int r = 0; r < 32; ++r)
        a = fmaf(sH[ks * 32 + r], w2p[(size_t)r * Rn], a);
    part[ks][col] = a;
    __syncthreads();
    if (tid < 64) {
        float t = part[0][tid] + part[1][tid] + part[2][tid] + part[3][tid];
        atomicAdd(&g_T[b * Rn + c0 + tid], t);
    }
}

// ---------------------------------------------------------------------------
// Kernel 5: logits = T @ wr + br ; aux loss + mode
// ---------------------------------------------------------------------------
__global__ void final_kernel(const float* __restrict__ wr, const float* __restrict__ br,
                             float* out, int out_size) {
    __shared__ float sl[64];
    const int t = threadIdx.x;
    if (t < 64) {
        const int b = t >> 3, e = t & 7;
        float lg = br[e];
        #pragma unroll 8
        for (int q = 0; q < Rn; ++q) lg = fmaf(g_T[b * Rn + q], wr[q * En + e], lg);
        sl[t] = lg;
    }
    __syncthreads();
    if (t == 0) {
        float aux = 0.f;
        int counts[En] = {};
        for (int b = 0; b < Bn; ++b) {
            const float* l = &sl[b * En];
            int best = 0;
            for (int e = 1; e < En; ++e)
                if (l[e] > l[best]) best = e;
            counts[best]++;
            for (int e = 0; e < En; ++e) {
                float x = l[e];
                float sp = fmaxf(x, 0.f) + log1pf(expf(-fabsf(x)));
                aux += sp - (e == best ? x : 0.f);
            }
        }
        aux *= (1.f / (Bn * En));
        int nxt = 0;
        for (int e = 1; e < En; ++e)
            if (counts[e] > counts[nxt]) nxt = e;
        out[0] = aux;
        if (out_size > 1) out[1] = (float)nxt;
    }
}

// ---------------------------------------------------------------------------
extern "C" void kernel_launch(void* const* d_in, const int* in_sizes, int n_in,
                              void* d_out, int out_size) {
    const float* hs    = (const float*)d_in[0];
    const float* gamma = (const float*)d_in[1];
    const float* beta  = (const float*)d_in[2];
    const float* w1    = (const float*)d_in[3];
    const float* b1    = (const float*)d_in[4];
    const float* w2    = (const float*)d_in[5];
    const float* b2    = (const float*)d_in[6];
    const float* wr    = (const float*)d_in[7];
    const float* br    = (const float*)d_in[8];

    cudaFuncSetAttribute(gemm_kernel, cudaFuncAttributeMaxDynamicSharedMemorySize, SMEM_BYTES);

    prep_kernel<<<(Dn * Rn + 255) / 256, 256>>>(w1, b2);  // idx 0
    ln_kernel<<<Mn, 256>>>(hs, gamma, beta);               // idx 1
    nop_kernel<<<1, 32>>>();                                // idx 2
    gemm_kernel<<<dim3(Rn / BN, Mn / BM), 256, SMEM_BYTES>>>(b1);  // idx 3 (profiled)
    tail_kernel<<<dim3(8, Bn, 4), 256>>>(w2);
    final_kernel<<<1, 64>>>(wr, br, (float*)d_out, out_size);
}